// round 5
// baseline (speedup 1.0000x reference)
#include <cuda_runtime.h>

#define N_NODES 50000
#define F1 32
#define F2 16

// ---------------- scratch (device globals; no allocation allowed) ----------
__device__ int   g_cnt_out[3][N_NODES];                  // out-degree counts
__device__ int   g_cnt_in [3][N_NODES];                  // in-degree counts
__device__ float g_rinv_out[3][N_NODES];                 // rsqrt(max(deg_out,1))
__device__ float g_rinv_in [3][N_NODES];                 // rsqrt(max(deg_in,1))
__device__ __align__(16) float g_h1[3][N_NODES * F2];    // per-relation pre-agg messages
__device__ __align__(16) float g_m [N_NODES * F2];       // combined layer-1 aggregate
__device__ float g_s  [3][N_NODES];                      // layer-2 scalar projections
__device__ float g_out[N_NODES];                         // layer-2 accumulator

// ---------------- K1: zero counters + aggregate + out ----------------------
__global__ void k_zero() {
    int i = blockIdx.x * blockDim.x + threadIdx.x;
    const int nd = 3 * N_NODES;
    if (i < nd)       ((int*)g_cnt_out)[i] = 0;
    if (i < nd)       ((int*)g_cnt_in)[i]  = 0;
    const int fm = N_NODES * F2;
    if (i < fm)       g_m[i] = 0.0f;
    if (i < N_NODES)  g_out[i] = 0.0f;
}

// ---------------- K2: degree counting (per relation, int atomics) ----------
__global__ void k_count(const int* __restrict__ src,
                        const int* __restrict__ dst, int E, int r) {
    int i = blockIdx.x * blockDim.x + threadIdx.x;
    if (i >= E) return;
    int s = src[i];
    int d = dst[i];
    atomicAdd(&g_cnt_out[r][s], 1);
    atomicAdd(&g_cnt_in [r][d], 1);
}

// ---------------- K3: counts -> rsqrt(max(deg,1)) --------------------------
__global__ void k_rinv() {
    int i = blockIdx.x * blockDim.x + threadIdx.x;
    const int nd = 3 * N_NODES;
    if (i >= nd) return;
    ((float*)g_rinv_out)[i] = rsqrtf(fmaxf((float)((const int*)g_cnt_out)[i], 1.0f));
    ((float*)g_rinv_in )[i] = rsqrtf(fmaxf((float)((const int*)g_cnt_in )[i], 1.0f));
}

// ---------------- K4: h1_r[n] = (x[n] * rinv_out_r[n]) @ W1[r] -------------
__global__ void k_h1(const float* __restrict__ x, const float* __restrict__ W1) {
    __shared__ float sW[3 * F1 * F2];
    for (int t = threadIdx.x; t < 3 * F1 * F2; t += blockDim.x) sW[t] = W1[t];
    __syncthreads();
    int n = blockIdx.x * blockDim.x + threadIdx.x;
    if (n >= N_NODES) return;

    float xr[F1];
    const float4* xp = (const float4*)(x + (size_t)n * F1);
#pragma unroll
    for (int k = 0; k < F1 / 4; k++) {
        float4 v = xp[k];
        xr[4 * k + 0] = v.x; xr[4 * k + 1] = v.y;
        xr[4 * k + 2] = v.z; xr[4 * k + 3] = v.w;
    }
#pragma unroll
    for (int r = 0; r < 3; r++) {
        float scale = g_rinv_out[r][n];
        float acc[F2];
#pragma unroll
        for (int j = 0; j < F2; j++) acc[j] = 0.0f;
        const float* wr = sW + r * F1 * F2;
#pragma unroll
        for (int i = 0; i < F1; i++) {
            float xv = xr[i];
#pragma unroll
            for (int j = 0; j < F2; j++) acc[j] = fmaf(xv, wr[i * F2 + j], acc[j]);
        }
        float4* op = (float4*)&g_h1[r][(size_t)n * F2];
#pragma unroll
        for (int k = 0; k < F2 / 4; k++) {
            float4 v;
            v.x = acc[4 * k + 0] * scale; v.y = acc[4 * k + 1] * scale;
            v.z = acc[4 * k + 2] * scale; v.w = acc[4 * k + 3] * scale;
            op[k] = v;
        }
    }
}

// ---------------- K5: layer-1 edge aggregation (per relation) --------------
// m[dst] += h1_r[src] * rinv_in_r[dst]; scalar float REDs into __device__ g_m.
__global__ void k_agg1(const int* __restrict__ src,
                       const int* __restrict__ dst, int E, int r) {
    int i = blockIdx.x * blockDim.x + threadIdx.x;
    if (i >= E) return;
    int s = src[i];
    int d = dst[i];
    float sc = g_rinv_in[r][d];
    const float4* hp = (const float4*)&g_h1[r][(size_t)s * F2];
    float* mp = &g_m[(size_t)d * F2];
#pragma unroll
    for (int k = 0; k < F2 / 4; k++) {
        float4 v = hp[k];
        atomicAdd(mp + 4 * k + 0, v.x * sc);
        atomicAdd(mp + 4 * k + 1, v.y * sc);
        atomicAdd(mp + 4 * k + 2, v.z * sc);
        atomicAdd(mp + 4 * k + 3, v.w * sc);
    }
}

// ---------------- K6: finish layer 1, project layer 2 ----------------------
__global__ void k_l2prep(const float* __restrict__ b1, const float* __restrict__ W2,
                         const float* __restrict__ b2) {
    __shared__ float sb1[F2];
    __shared__ float sW2[3][F2];
    __shared__ float sb2sum;
    if (threadIdx.x < F2)
        sb1[threadIdx.x] = b1[threadIdx.x] + b1[F2 + threadIdx.x] + b1[2 * F2 + threadIdx.x];
    if (threadIdx.x < 3 * F2)
        sW2[threadIdx.x / F2][threadIdx.x % F2] = W2[threadIdx.x];
    if (threadIdx.x == 0) sb2sum = b2[0] + b2[1] + b2[2];
    __syncthreads();

    int n = blockIdx.x * blockDim.x + threadIdx.x;
    if (n >= N_NODES) return;

    float h[F2];
    const float4* mp = (const float4*)&g_m[(size_t)n * F2];
#pragma unroll
    for (int k = 0; k < F2 / 4; k++) {
        float4 v = mp[k];
        h[4 * k + 0] = v.x; h[4 * k + 1] = v.y;
        h[4 * k + 2] = v.z; h[4 * k + 3] = v.w;
    }
#pragma unroll
    for (int j = 0; j < F2; j++) h[j] = fmaxf(h[j] + sb1[j], 0.0f);

#pragma unroll
    for (int r = 0; r < 3; r++) {
        float dot = 0.0f;
#pragma unroll
        for (int j = 0; j < F2; j++) dot = fmaf(h[j], sW2[r][j], dot);
        g_s[r][n] = dot * g_rinv_out[r][n];
    }
    g_out[n] = sb2sum;
}

// ---------------- K7: layer-2 edge aggregation (into g_out) ----------------
__global__ void k_agg2(const int* __restrict__ src,
                       const int* __restrict__ dst, int E, int r) {
    int i = blockIdx.x * blockDim.x + threadIdx.x;
    if (i >= E) return;
    int s = src[i];
    int d = dst[i];
    atomicAdd(&g_out[d], g_s[r][s] * g_rinv_in[r][d]);
}

// ---------------- K8: plain-store copy to harness d_out --------------------
__global__ void k_final(float* __restrict__ out) {
    int n = blockIdx.x * blockDim.x + threadIdx.x;
    if (n < N_NODES) out[n] = g_out[n];
}

// ---------------- launch ----------------------------------------------------
extern "C" void kernel_launch(void* const* d_in, const int* in_sizes, int n_in,
                              void* d_out, int out_size) {
    const float* x = (const float*)d_in[0];
    const int* src[3] = {(const int*)d_in[1], (const int*)d_in[3], (const int*)d_in[5]};
    const int* dst[3] = {(const int*)d_in[2], (const int*)d_in[4], (const int*)d_in[6]};
    int E[3] = {in_sizes[1], in_sizes[3], in_sizes[5]};
    const float* W1 = (const float*)d_in[7];
    const float* b1 = (const float*)d_in[8];
    const float* W2 = (const float*)d_in[9];
    const float* b2 = (const float*)d_in[10];
    float* out = (float*)d_out;

    const int T = 256;
    int zgrid = (N_NODES * F2 + T - 1) / T;   // covers all zeroed ranges
    k_zero<<<zgrid, T>>>();
    for (int r = 0; r < 3; r++)
        k_count<<<(E[r] + T - 1) / T, T>>>(src[r], dst[r], E[r], r);
    k_rinv<<<(3 * N_NODES + T - 1) / T, T>>>();
    k_h1<<<(N_NODES + T - 1) / T, T>>>(x, W1);
    for (int r = 0; r < 3; r++)
        k_agg1<<<(E[r] + T - 1) / T, T>>>(src[r], dst[r], E[r], r);
    k_l2prep<<<(N_NODES + T - 1) / T, T>>>(b1, W2, b2);
    for (int r = 0; r < 3; r++)
        k_agg2<<<(E[r] + T - 1) / T, T>>>(src[r], dst[r], E[r], r);
    k_final<<<(N_NODES + T - 1) / T, T>>>(out);
}

// round 6
// speedup vs baseline: 1.8983x; 1.8983x over previous
#include <cuda_runtime.h>

#define N_NODES 50000
#define F1 32
#define F2 16

// ---------------- scratch (device globals; no allocation allowed) ----------
__device__ int   g_cnt_out[3][N_NODES];                  // out-degree counts
__device__ int   g_cnt_in [3][N_NODES];                  // in-degree counts
__device__ float g_rinv_out[3][N_NODES];                 // rsqrt(max(deg_out,1))
__device__ float g_rinv_in [3][N_NODES];                 // rsqrt(max(deg_in,1))
__device__ __align__(16) float g_h1[3][N_NODES * F2];    // per-relation pre-agg messages
__device__ __align__(16) float g_m [3][N_NODES * F2];    // per-relation raw aggregates
__device__ float g_s   [3][N_NODES];                     // layer-2 scalar projections
__device__ float g_out3[3][N_NODES];                     // layer-2 raw accumulators

// ---------------- K1: zero counters + aggregates -----------------------------
__global__ void k_zero() {
    int i = blockIdx.x * blockDim.x + threadIdx.x;
    const int nd = 3 * N_NODES;
    if (i < nd) {
        ((int*)g_cnt_out)[i] = 0;
        ((int*)g_cnt_in)[i]  = 0;
        ((float*)g_out3)[i]  = 0.0f;
    }
    const int fm = 3 * N_NODES * F2;
    if (i < fm) ((float*)g_m)[i] = 0.0f;
}

// ---------------- K2: degree counting (per relation, int atomics) ----------
__global__ void k_count(const int* __restrict__ src,
                        const int* __restrict__ dst, int E, int r) {
    int i = blockIdx.x * blockDim.x + threadIdx.x;
    if (i >= E) return;
    atomicAdd(&g_cnt_out[r][src[i]], 1);
    atomicAdd(&g_cnt_in [r][dst[i]], 1);
}

// ---------------- K3: counts -> rsqrt(max(deg,1)) --------------------------
__global__ void k_rinv() {
    int i = blockIdx.x * blockDim.x + threadIdx.x;
    const int nd = 3 * N_NODES;
    if (i >= nd) return;
    ((float*)g_rinv_out)[i] = rsqrtf(fmaxf((float)((const int*)g_cnt_out)[i], 1.0f));
    ((float*)g_rinv_in )[i] = rsqrtf(fmaxf((float)((const int*)g_cnt_in )[i], 1.0f));
}

// ---------------- K4: h1_r[n] = (x[n] * rinv_out_r[n]) @ W1[r] -------------
__global__ void k_h1(const float* __restrict__ x, const float* __restrict__ W1) {
    __shared__ float sW[3 * F1 * F2];
    for (int t = threadIdx.x; t < 3 * F1 * F2; t += blockDim.x) sW[t] = W1[t];
    __syncthreads();
    int n = blockIdx.x * blockDim.x + threadIdx.x;
    if (n >= N_NODES) return;

    float xr[F1];
    const float4* xp = (const float4*)(x + (size_t)n * F1);
#pragma unroll
    for (int k = 0; k < F1 / 4; k++) {
        float4 v = xp[k];
        xr[4 * k + 0] = v.x; xr[4 * k + 1] = v.y;
        xr[4 * k + 2] = v.z; xr[4 * k + 3] = v.w;
    }
#pragma unroll
    for (int r = 0; r < 3; r++) {
        float scale = g_rinv_out[r][n];
        float acc[F2];
#pragma unroll
        for (int j = 0; j < F2; j++) acc[j] = 0.0f;
        const float* wr = sW + r * F1 * F2;
#pragma unroll
        for (int i = 0; i < F1; i++) {
            float xv = xr[i];
#pragma unroll
            for (int j = 0; j < F2; j++) acc[j] = fmaf(xv, wr[i * F2 + j], acc[j]);
        }
        float4* op = (float4*)&g_h1[r][(size_t)n * F2];
#pragma unroll
        for (int k = 0; k < F2 / 4; k++) {
            float4 v;
            v.x = acc[4 * k + 0] * scale; v.y = acc[4 * k + 1] * scale;
            v.z = acc[4 * k + 2] * scale; v.w = acc[4 * k + 3] * scale;
            op[k] = v;
        }
    }
}

// ---------------- K5: layer-1 edge aggregation (per relation) --------------
// m_r[dst] += h1_r[src]  (raw sum; rinv_in applied later per node).
// 4x RED.128 per edge via vector atomicAdd (sm_90+).
__global__ void k_agg1(const int* __restrict__ src,
                       const int* __restrict__ dst, int E, int r) {
    int i = blockIdx.x * blockDim.x + threadIdx.x;
    if (i >= E) return;
    int s = src[i];
    int d = dst[i];
    const float4* hp = (const float4*)&g_h1[r][(size_t)s * F2];
    float4* mp = (float4*)&g_m[r][(size_t)d * F2];
#pragma unroll
    for (int k = 0; k < F2 / 4; k++) {
        atomicAdd(mp + k, hp[k]);
    }
}

// ---------------- K6: finish layer 1, project layer 2 ----------------------
// h[n] = relu( sum_r rinv_in_r[n]*m_r[n] + sum_r b1[r] )
// g_s[r][n] = rinv_out_r[n] * (h[n] . W2[r])
__global__ void k_l2prep(const float* __restrict__ b1, const float* __restrict__ W2) {
    __shared__ float sb1[F2];
    __shared__ float sW2[3][F2];
    if (threadIdx.x < F2)
        sb1[threadIdx.x] = b1[threadIdx.x] + b1[F2 + threadIdx.x] + b1[2 * F2 + threadIdx.x];
    if (threadIdx.x < 3 * F2)
        sW2[threadIdx.x / F2][threadIdx.x % F2] = W2[threadIdx.x];
    __syncthreads();

    int n = blockIdx.x * blockDim.x + threadIdx.x;
    if (n >= N_NODES) return;

    float h[F2];
#pragma unroll
    for (int j = 0; j < F2; j++) h[j] = sb1[j];
#pragma unroll
    for (int r = 0; r < 3; r++) {
        float ri = g_rinv_in[r][n];
        const float4* mp = (const float4*)&g_m[r][(size_t)n * F2];
#pragma unroll
        for (int k = 0; k < F2 / 4; k++) {
            float4 v = mp[k];
            h[4 * k + 0] = fmaf(v.x, ri, h[4 * k + 0]);
            h[4 * k + 1] = fmaf(v.y, ri, h[4 * k + 1]);
            h[4 * k + 2] = fmaf(v.z, ri, h[4 * k + 2]);
            h[4 * k + 3] = fmaf(v.w, ri, h[4 * k + 3]);
        }
    }
#pragma unroll
    for (int j = 0; j < F2; j++) h[j] = fmaxf(h[j], 0.0f);

#pragma unroll
    for (int r = 0; r < 3; r++) {
        float dot = 0.0f;
#pragma unroll
        for (int j = 0; j < F2; j++) dot = fmaf(h[j], sW2[r][j], dot);
        g_s[r][n] = dot * g_rinv_out[r][n];
    }
}

// ---------------- K7: layer-2 edge aggregation (raw, per relation) ---------
__global__ void k_agg2(const int* __restrict__ src,
                       const int* __restrict__ dst, int E, int r) {
    int i = blockIdx.x * blockDim.x + threadIdx.x;
    if (i >= E) return;
    atomicAdd(&g_out3[r][dst[i]], g_s[r][src[i]]);
}

// ---------------- K8: final: scale + bias + store to d_out -----------------
__global__ void k_final(const float* __restrict__ b2, float* __restrict__ out) {
    __shared__ float sb2sum;
    if (threadIdx.x == 0) sb2sum = b2[0] + b2[1] + b2[2];
    __syncthreads();
    int n = blockIdx.x * blockDim.x + threadIdx.x;
    if (n >= N_NODES) return;
    float v = sb2sum;
#pragma unroll
    for (int r = 0; r < 3; r++)
        v = fmaf(g_out3[r][n], g_rinv_in[r][n], v);
    out[n] = v;
}

// ---------------- launch ----------------------------------------------------
extern "C" void kernel_launch(void* const* d_in, const int* in_sizes, int n_in,
                              void* d_out, int out_size) {
    const float* x = (const float*)d_in[0];
    const int* src[3] = {(const int*)d_in[1], (const int*)d_in[3], (const int*)d_in[5]};
    const int* dst[3] = {(const int*)d_in[2], (const int*)d_in[4], (const int*)d_in[6]};
    int E[3] = {in_sizes[1], in_sizes[3], in_sizes[5]};
    const float* W1 = (const float*)d_in[7];
    const float* b1 = (const float*)d_in[8];
    const float* W2 = (const float*)d_in[9];
    const float* b2 = (const float*)d_in[10];
    float* out = (float*)d_out;

    const int T = 256;
    int zgrid = (3 * N_NODES * F2 + T - 1) / T;   // covers all zeroed ranges
    k_zero<<<zgrid, T>>>();
    for (int r = 0; r < 3; r++)
        k_count<<<(E[r] + T - 1) / T, T>>>(src[r], dst[r], E[r], r);
    k_rinv<<<(3 * N_NODES + T - 1) / T, T>>>();
    k_h1<<<(N_NODES + T - 1) / T, T>>>(x, W1);
    for (int r = 0; r < 3; r++)
        k_agg1<<<(E[r] + T - 1) / T, T>>>(src[r], dst[r], E[r], r);
    k_l2prep<<<(N_NODES + T - 1) / T, T>>>(b1, W2);
    for (int r = 0; r < 3; r++)
        k_agg2<<<(E[r] + T - 1) / T, T>>>(src[r], dst[r], E[r], r);
    k_final<<<(N_NODES + T - 1) / T, T>>>(b2, out);
}

// round 9
// speedup vs baseline: 2.0906x; 1.1013x over previous
#include <cuda_runtime.h>

#define N_NODES 50000
#define F1 32
#define F2 16
#define EPT 4          // edges per thread in edge kernels
#define T 256          // threads per block

// ---------------- scratch (device globals; no allocation allowed) ----------
__device__ int   g_cnt_out[3][N_NODES];                  // out-degree counts
__device__ int   g_cnt_in [3][N_NODES];                  // in-degree counts
__device__ __align__(16) float g_h1[3][N_NODES * F2];    // per-relation pre-agg messages
__device__ __align__(16) float g_m [3][N_NODES * F2];    // per-relation raw aggregates
__device__ float g_s   [3][N_NODES];                     // layer-2 scalar projections
__device__ float g_out3[3][N_NODES];                     // layer-2 raw accumulators

__device__ __forceinline__ float rinv_of(int c) {
    return rsqrtf(fmaxf((float)c, 1.0f));
}

// Map fused blockIdx -> (relation, local block)
struct RelSel { const int* s; const int* d; int E; int r; int b; };
__device__ __forceinline__ RelSel pick_rel(
    int b, const int* s0, const int* d0, int E0, int B0,
    const int* s1, const int* d1, int E1, int B1,
    const int* s2, const int* d2, int E2) {
    RelSel rs;
    if (b < B0)            { rs = {s0, d0, E0, 0, b}; }
    else if (b < B0 + B1)  { rs = {s1, d1, E1, 1, b - B0}; }
    else                   { rs = {s2, d2, E2, 2, b - B0 - B1}; }
    return rs;
}

// ---------------- K1: zero counters + aggregates ---------------------------
__global__ void k_zero() {
    int i = blockIdx.x * blockDim.x + threadIdx.x;
    const int nd = 3 * N_NODES;
    if (i < nd) {
        ((int*)g_cnt_out)[i] = 0;
        ((int*)g_cnt_in)[i]  = 0;
        ((float*)g_out3)[i]  = 0.0f;
    }
    const int fm = 3 * N_NODES * F2;
    if (i < fm) ((float*)g_m)[i] = 0.0f;
}

// ---------------- K2: fused degree counting (all relations) ----------------
__global__ void k_count_all(const int* __restrict__ s0, const int* __restrict__ d0, int E0, int B0,
                            const int* __restrict__ s1, const int* __restrict__ d1, int E1, int B1,
                            const int* __restrict__ s2, const int* __restrict__ d2, int E2) {
    RelSel rs = pick_rel(blockIdx.x, s0, d0, E0, B0, s1, d1, E1, B1, s2, d2, E2);
    int i0 = (rs.b * T + threadIdx.x) * EPT;
    int* co = &g_cnt_out[rs.r][0];
    int* ci = &g_cnt_in [rs.r][0];
    if (i0 + EPT <= rs.E) {
        int4 sv = *(const int4*)(rs.s + i0);
        int4 dv = *(const int4*)(rs.d + i0);
        atomicAdd(co + sv.x, 1); atomicAdd(co + sv.y, 1);
        atomicAdd(co + sv.z, 1); atomicAdd(co + sv.w, 1);
        atomicAdd(ci + dv.x, 1); atomicAdd(ci + dv.y, 1);
        atomicAdd(ci + dv.z, 1); atomicAdd(ci + dv.w, 1);
    } else {
        for (int i = i0; i < rs.E; i++) {
            atomicAdd(co + rs.s[i], 1);
            atomicAdd(ci + rs.d[i], 1);
        }
    }
}

// ---------------- K3: h1_r[n] = (x[n] * rinv_out_r[n]) @ W1[r] -------------
__global__ void k_h1(const float* __restrict__ x, const float* __restrict__ W1) {
    __shared__ float sW[3 * F1 * F2];
    for (int t = threadIdx.x; t < 3 * F1 * F2; t += blockDim.x) sW[t] = W1[t];
    __syncthreads();
    int n = blockIdx.x * blockDim.x + threadIdx.x;
    if (n >= N_NODES) return;

    float xr[F1];
    const float4* xp = (const float4*)(x + (size_t)n * F1);
#pragma unroll
    for (int k = 0; k < F1 / 4; k++) {
        float4 v = xp[k];
        xr[4 * k + 0] = v.x; xr[4 * k + 1] = v.y;
        xr[4 * k + 2] = v.z; xr[4 * k + 3] = v.w;
    }
#pragma unroll
    for (int r = 0; r < 3; r++) {
        float scale = rinv_of(g_cnt_out[r][n]);
        float acc[F2];
#pragma unroll
        for (int j = 0; j < F2; j++) acc[j] = 0.0f;
        const float* wr = sW + r * F1 * F2;
#pragma unroll
        for (int i = 0; i < F1; i++) {
            float xv = xr[i];
#pragma unroll
            for (int j = 0; j < F2; j++) acc[j] = fmaf(xv, wr[i * F2 + j], acc[j]);
        }
        float4* op = (float4*)&g_h1[r][(size_t)n * F2];
#pragma unroll
        for (int k = 0; k < F2 / 4; k++) {
            float4 v;
            v.x = acc[4 * k + 0] * scale; v.y = acc[4 * k + 1] * scale;
            v.z = acc[4 * k + 2] * scale; v.w = acc[4 * k + 3] * scale;
            op[k] = v;
        }
    }
}

// ---------------- K4: fused layer-1 aggregation (all relations) ------------
// m_r[dst] += h1_r[src]; 4x RED.128 per edge; 4 edges per thread for MLP.
__global__ void k_agg1_all(const int* __restrict__ s0, const int* __restrict__ d0, int E0, int B0,
                           const int* __restrict__ s1, const int* __restrict__ d1, int E1, int B1,
                           const int* __restrict__ s2, const int* __restrict__ d2, int E2) {
    RelSel rs = pick_rel(blockIdx.x, s0, d0, E0, B0, s1, d1, E1, B1, s2, d2, E2);
    int i0 = (rs.b * T + threadIdx.x) * EPT;
    const float4* h1 = (const float4*)&g_h1[rs.r][0];
    float4*       m  = (float4*)&g_m [rs.r][0];
    if (i0 + EPT <= rs.E) {
        int4 sv = *(const int4*)(rs.s + i0);
        int4 dv = *(const int4*)(rs.d + i0);
        int ss[EPT] = {sv.x, sv.y, sv.z, sv.w};
        int dd[EPT] = {dv.x, dv.y, dv.z, dv.w};
        float4 msg[EPT][F2 / 4];
#pragma unroll
        for (int e = 0; e < EPT; e++) {
            const float4* hp = h1 + (size_t)ss[e] * (F2 / 4);
#pragma unroll
            for (int k = 0; k < F2 / 4; k++) msg[e][k] = hp[k];
        }
#pragma unroll
        for (int e = 0; e < EPT; e++) {
            float4* mp = m + (size_t)dd[e] * (F2 / 4);
#pragma unroll
            for (int k = 0; k < F2 / 4; k++) atomicAdd(mp + k, msg[e][k]);
        }
    } else {
        for (int i = i0; i < rs.E; i++) {
            const float4* hp = h1 + (size_t)rs.s[i] * (F2 / 4);
            float4* mp = m + (size_t)rs.d[i] * (F2 / 4);
#pragma unroll
            for (int k = 0; k < F2 / 4; k++) atomicAdd(mp + k, hp[k]);
        }
    }
}

// ---------------- K5: finish layer 1, project layer 2 ----------------------
__global__ void k_l2prep(const float* __restrict__ b1, const float* __restrict__ W2) {
    __shared__ float sb1[F2];
    __shared__ float sW2[3][F2];
    if (threadIdx.x < F2)
        sb1[threadIdx.x] = b1[threadIdx.x] + b1[F2 + threadIdx.x] + b1[2 * F2 + threadIdx.x];
    if (threadIdx.x < 3 * F2)
        sW2[threadIdx.x / F2][threadIdx.x % F2] = W2[threadIdx.x];
    __syncthreads();

    int n = blockIdx.x * blockDim.x + threadIdx.x;
    if (n >= N_NODES) return;

    float h[F2];
#pragma unroll
    for (int j = 0; j < F2; j++) h[j] = sb1[j];
#pragma unroll
    for (int r = 0; r < 3; r++) {
        float ri = rinv_of(g_cnt_in[r][n]);
        const float4* mp = (const float4*)&g_m[r][(size_t)n * F2];
#pragma unroll
        for (int k = 0; k < F2 / 4; k++) {
            float4 v = mp[k];
            h[4 * k + 0] = fmaf(v.x, ri, h[4 * k + 0]);
            h[4 * k + 1] = fmaf(v.y, ri, h[4 * k + 1]);
            h[4 * k + 2] = fmaf(v.z, ri, h[4 * k + 2]);
            h[4 * k + 3] = fmaf(v.w, ri, h[4 * k + 3]);
        }
    }
#pragma unroll
    for (int j = 0; j < F2; j++) h[j] = fmaxf(h[j], 0.0f);

#pragma unroll
    for (int r = 0; r < 3; r++) {
        float dot = 0.0f;
#pragma unroll
        for (int j = 0; j < F2; j++) dot = fmaf(h[j], sW2[r][j], dot);
        g_s[r][n] = dot * rinv_of(g_cnt_out[r][n]);
    }
}

// ---------------- K6: fused layer-2 aggregation (all relations) ------------
__global__ void k_agg2_all(const int* __restrict__ s0, const int* __restrict__ d0, int E0, int B0,
                           const int* __restrict__ s1, const int* __restrict__ d1, int E1, int B1,
                           const int* __restrict__ s2, const int* __restrict__ d2, int E2) {
    RelSel rs = pick_rel(blockIdx.x, s0, d0, E0, B0, s1, d1, E1, B1, s2, d2, E2);
    int i0 = (rs.b * T + threadIdx.x) * EPT;
    const float* sc = &g_s[rs.r][0];
    float* ob = &g_out3[rs.r][0];
    if (i0 + EPT <= rs.E) {
        int4 sv = *(const int4*)(rs.s + i0);
        int4 dv = *(const int4*)(rs.d + i0);
        float v0 = sc[sv.x], v1 = sc[sv.y], v2 = sc[sv.z], v3 = sc[sv.w];
        atomicAdd(ob + dv.x, v0); atomicAdd(ob + dv.y, v1);
        atomicAdd(ob + dv.z, v2); atomicAdd(ob + dv.w, v3);
    } else {
        for (int i = i0; i < rs.E; i++)
            atomicAdd(ob + rs.d[i], sc[rs.s[i]]);
    }
}

// ---------------- K7: final: scale + bias + store to d_out -----------------
__global__ void k_final(const float* __restrict__ b2, float* __restrict__ out) {
    __shared__ float sb2sum;
    if (threadIdx.x == 0) sb2sum = b2[0] + b2[1] + b2[2];
    __syncthreads();
    int n = blockIdx.x * blockDim.x + threadIdx.x;
    if (n >= N_NODES) return;
    float v = sb2sum;
#pragma unroll
    for (int r = 0; r < 3; r++)
        v = fmaf(g_out3[r][n], rinv_of(g_cnt_in[r][n]), v);
    out[n] = v;
}

// ---------------- launch ----------------------------------------------------
extern "C" void kernel_launch(void* const* d_in, const int* in_sizes, int n_in,
                              void* d_out, int out_size) {
    const float* x = (const float*)d_in[0];
    const int* s0 = (const int*)d_in[1]; const int* d0 = (const int*)d_in[2];
    const int* s1 = (const int*)d_in[3]; const int* d1 = (const int*)d_in[4];
    const int* s2 = (const int*)d_in[5]; const int* d2 = (const int*)d_in[6];
    int E0 = in_sizes[1], E1 = in_sizes[3], E2 = in_sizes[5];
    const float* W1 = (const float*)d_in[7];
    const float* b1 = (const float*)d_in[8];
    const float* W2 = (const float*)d_in[9];
    const float* b2 = (const float*)d_in[10];
    float* out = (float*)d_out;

    const int PER_BLK = T * EPT;
    int B0 = (E0 + PER_BLK - 1) / PER_BLK;
    int B1 = (E1 + PER_BLK - 1) / PER_BLK;
    int B2 = (E2 + PER_BLK - 1) / PER_BLK;
    int BE = B0 + B1 + B2;

    int zgrid = (3 * N_NODES * F2 + T - 1) / T;
    k_zero<<<zgrid, T>>>();
    k_count_all<<<BE, T>>>(s0, d0, E0, B0, s1, d1, E1, B1, s2, d2, E2);
    k_h1<<<(N_NODES + T - 1) / T, T>>>(x, W1);
    k_agg1_all<<<BE, T>>>(s0, d0, E0, B0, s1, d1, E1, B1, s2, d2, E2);
    k_l2prep<<<(N_NODES + T - 1) / T, T>>>(b1, W2);
    k_agg2_all<<<BE, T>>>(s0, d0, E0, B0, s1, d1, E1, B1, s2, d2, E2);
    k_final<<<(N_NODES + T - 1) / T, T>>>(b2, out);
}